// round 15
// baseline (speedup 1.0000x reference)
#include <cuda_runtime.h>
#include <math.h>

#define B_  8
#define T_  4096
#define H_  4
#define HV_ 8
#define K_  128
#define V_  128
#define REP_ (HV_/H_)   // 2
#define S4_ (T_/4)      // fused 4-step groups (quads)
#define CHS 16          // steps per smem chunk
#define CHQ (CHS/4)     // quads per chunk = 4
#define NCH (T_/CHS)    // 256 chunks

// smem layout: stream row = 8 octants * 80B (16B pad) = 640B; step = 1280B.
#define ROWB  640
#define STEPB 1280
#define BUFB  (CHS*STEPB)   // 20480B per buffer, x2 double-buffered

// Scratch (static __device__ arrays: allocation-free per harness rules)
__device__ float  g_qn[(size_t)B_*T_*H_*K_];    // l2norm q * K^-0.5
__device__ float  g_kn[(size_t)B_*T_*H_*K_];    // l2norm k
__device__ float4 g_d4[(size_t)B_*S4_*H_*4];    // 16 cross dots per quad
__device__ float4 g_g8[(size_t)B_*S4_*HV_*2];   // {eg1..4},{beta1..4} per quad

// ---------------------------------------------------------------------------
// Prepass 1: per (b,t,h) row — l2norm q and k over K=128, fold scale into q.
// ---------------------------------------------------------------------------
__global__ void __launch_bounds__(128) prep_qk(const float* __restrict__ q,
                                               const float* __restrict__ k) {
    int warp = threadIdx.x >> 5;
    int lane = threadIdx.x & 31;
    size_t row = (size_t)blockIdx.x * 4 + warp;
    const float4* q4 = reinterpret_cast<const float4*>(q + row * K_);
    const float4* k4 = reinterpret_cast<const float4*>(k + row * K_);
    float4 qa = q4[lane];
    float4 ka = k4[lane];
    float sq = qa.x*qa.x + qa.y*qa.y + qa.z*qa.z + qa.w*qa.w;
    float sk = ka.x*ka.x + ka.y*ka.y + ka.z*ka.z + ka.w*ka.w;
    #pragma unroll
    for (int o = 16; o > 0; o >>= 1) {
        sq += __shfl_xor_sync(0xffffffffu, sq, o);
        sk += __shfl_xor_sync(0xffffffffu, sk, o);
    }
    const float scale = 0.088388347648318440550f;   // 128^-0.5
    float iq = rsqrtf(sq + 1e-6f) * scale;
    float ik = rsqrtf(sk + 1e-6f);
    reinterpret_cast<float4*>(g_qn + row * K_)[lane] =
        make_float4(qa.x*iq, qa.y*iq, qa.z*iq, qa.w*iq);
    reinterpret_cast<float4*>(g_kn + row * K_)[lane] =
        make_float4(ka.x*ik, ka.y*ik, ka.z*ik, ka.w*ik);
}

__device__ __forceinline__ float dot4(float4 a, float4 b) {
    return a.x*b.x + a.y*b.y + a.z*b.z + a.w*b.w;
}

// ---------------------------------------------------------------------------
// Prepass 1b: per quad (b,s4,h) — the 16 cross dots among steps 4s..4s+3:
//   Kij = k_i.k_j (i<j): K12 K13 K14 K23 K24 K34
//   Qij = k_i.q_j (i<=j): Q11 Q12 Q13 Q14 Q22 Q23 Q24 Q33 Q34 Q44
// One warp per quad; packed as 4 consecutive float4s.
// ---------------------------------------------------------------------------
__global__ void __launch_bounds__(128) prep_dots4() {
    int warp = threadIdx.x >> 5;
    int lane = threadIdx.x & 31;
    size_t gid  = (size_t)blockIdx.x * 4 + warp;     // (b*S4 + s)*H + hh
    size_t hh   = gid % H_;
    size_t bs4  = gid / H_;
    size_t row0 = bs4 * 4 * H_ + hh;                 // (b*T + 4s)*H + hh
    float4 kr[4], qr[4];
    #pragma unroll
    for (int i = 0; i < 4; i++) {
        kr[i] = reinterpret_cast<const float4*>(g_kn + (row0 + (size_t)i*H_) * K_)[lane];
        qr[i] = reinterpret_cast<const float4*>(g_qn + (row0 + (size_t)i*H_) * K_)[lane];
    }
    float d[16];
    d[ 0] = dot4(kr[0], kr[1]);  // K12
    d[ 1] = dot4(kr[0], kr[2]);  // K13
    d[ 2] = dot4(kr[0], kr[3]);  // K14
    d[ 3] = dot4(kr[1], kr[2]);  // K23
    d[ 4] = dot4(kr[1], kr[3]);  // K24
    d[ 5] = dot4(kr[2], kr[3]);  // K34
    d[ 6] = dot4(kr[0], qr[0]);  // Q11
    d[ 7] = dot4(kr[0], qr[1]);  // Q12
    d[ 8] = dot4(kr[0], qr[2]);  // Q13
    d[ 9] = dot4(kr[0], qr[3]);  // Q14
    d[10] = dot4(kr[1], qr[1]);  // Q22
    d[11] = dot4(kr[1], qr[2]);  // Q23
    d[12] = dot4(kr[1], qr[3]);  // Q24
    d[13] = dot4(kr[2], qr[2]);  // Q33
    d[14] = dot4(kr[2], qr[3]);  // Q34
    d[15] = dot4(kr[3], qr[3]);  // Q44
    #pragma unroll
    for (int o = 16; o > 0; o >>= 1)
        #pragma unroll
        for (int i = 0; i < 16; i++)
            d[i] += __shfl_xor_sync(0xffffffffu, d[i], o);
    if (lane == 0) {
        g_d4[gid*4 + 0] = make_float4(d[ 0], d[ 1], d[ 2], d[ 3]);
        g_d4[gid*4 + 1] = make_float4(d[ 4], d[ 5], d[ 6], d[ 7]);
        g_d4[gid*4 + 2] = make_float4(d[ 8], d[ 9], d[10], d[11]);
        g_d4[gid*4 + 3] = make_float4(d[12], d[13], d[14], d[15]);
    }
}

// ---------------------------------------------------------------------------
// Prepass 2: per quad (b,s4,hv) — gates for 4 steps: {eg1..4},{beta1..4}.
// ---------------------------------------------------------------------------
__global__ void __launch_bounds__(256) prep_gate8(const float* __restrict__ A_log,
                                                  const float* __restrict__ a,
                                                  const float* __restrict__ dt_bias,
                                                  const float* __restrict__ b) {
    size_t i = (size_t)blockIdx.x * blockDim.x + threadIdx.x;   // (b*S4+s)*HV+hv
    if (i >= (size_t)B_*S4_*HV_) return;
    int    hv  = (int)(i % HV_);
    size_t bs4 = i / HV_;
    float  Ae  = expf(A_log[hv]);
    float eg[4], bt[4];
    #pragma unroll
    for (int u = 0; u < 4; u++) {
        size_t idx = (4*bs4 + u) * HV_ + hv;
        float x  = a[idx] + dt_bias[hv];
        float sp = (x <= 20.0f) ? log1pf(expf(x)) : x;   // softplus
        eg[u] = expf(-Ae * sp);
        bt[u] = 1.0f / (1.0f + expf(-b[idx]));
    }
    g_g8[i*2 + 0] = make_float4(eg[0], eg[1], eg[2], eg[3]);
    g_g8[i*2 + 1] = make_float4(bt[0], bt[1], bt[2], bt[3]);
}

// ---------------------------------------------------------------------------
// Main persistent recurrence, 4-step fused, smem-staged k/q.
// grid = 128 CTAs, 256 threads (2 warps/SMSP — the R11 balance point: smem
// crossbar bytes scale with thread count, so 512 thr was L1-bound in R13).
//   ko = tid&7 (16 k-rows), vg = tid>>3 (2 adjacent V cols)
// Per quad (4 steps): 8 dots vs OLD h (k1..4,q1..4, 2 cols = 16 accumulators)
//   -> ONE 3-round shfl reduce -> one scalar cascade (cross terms from g_d4)
//   -> h = E*h + c1*k1 + c2*k2 + c3*k3 + c4*k4.
// Halves the serial reduce+cascade exposure per step vs 2-step fusion.
// ---------------------------------------------------------------------------
__global__ void __launch_bounds__(256, 1) gdn_recurrent(
    const float* __restrict__ vin,
    const float* __restrict__ h0src,
    const int*   __restrict__ h0idx,
    float* __restrict__ out)
{
    __shared__ __align__(16) char smem[2 * BUFB];   // 40 KB

    int blk   = blockIdx.x;
    int vhalf = blk & 1;
    int hv    = (blk >> 1) & (HV_ - 1);
    int b     = blk >> 4;
    int tid   = threadIdx.x;
    int ko    = tid & 7;          // K-octant: rows [ko*16, ko*16+16)
    int vg    = tid >> 3;         // 0..31 -> V columns vg*2, vg*2+1
    int v0    = vhalf * 64 + vg * 2;
    int hh    = hv / REP_;

    // State tile: h[i] = k-row (ko*16+i), columns (v0, v0+1)
    float2 h[16];
    int idx = h0idx[b];
    if (idx >= 0) {
        const float* src = h0src + (((size_t)idx * HV_ + hv) * K_ + (size_t)ko * 16) * V_ + v0;
        #pragma unroll
        for (int i = 0; i < 16; i++)
            h[i] = *reinterpret_cast<const float2*>(src + (size_t)i * V_);
    } else {
        #pragma unroll
        for (int i = 0; i < 16; i++) h[i] = make_float2(0.f, 0.f);
    }

    const int VSTR = HV_ * V_ / 2;      // float2 stride per t-step

    const float*  kgm = g_kn + ((size_t)b*T_*H_ + hh)*K_;   // chunk staging bases
    const float*  qgm = g_qn + ((size_t)b*T_*H_ + hh)*K_;
    const float4* ddp = g_d4 + ((size_t)b*S4_*H_  + hh) * 4;
    const float4* ggp = g_g8 + ((size_t)b*S4_*HV_ + hv) * 2;
    const float2* vp  = reinterpret_cast<const float2*>(vin + ((size_t)b*T_*HV_ + hv)*V_ + v0);
    float2*       op  = reinterpret_cast<float2*>(out + ((size_t)b*T_*HV_ + hv)*V_ + v0);

    // Staging decode (identical to R11): 256 threads, 4 float4/thread/chunk.
    int s_step[4], s_soff[4], s_woff[4];
    #pragma unroll
    for (int r = 0; r < 4; r++) {
        int fidx = tid + 256 * r;
        int step = fidx >> 6;
        int w16  = fidx & 31;
        s_step[r] = step;
        s_woff[r] = w16 * 4;
        s_soff[r] = step * STEPB + ((fidx >> 5) & 1) * ROWB
                  + (w16 >> 2) * 80 + (w16 & 3) * 16;
    }

    #define STAGE(CH, BUF)                                                     \
    {                                                                          \
        const float* kb = kgm + (size_t)(CH) * CHS * (H_ * K_);                \
        const float* qb = qgm + (size_t)(CH) * CHS * (H_ * K_);                \
        char* dst = smem + (BUF) * BUFB;                                       \
        _Pragma("unroll")                                                      \
        for (int r = 0; r < 4; r++) {                                          \
            const float* srcb = ((tid + 256*r) & 32) ? qb : kb;                \
            float4 val = *reinterpret_cast<const float4*>(                     \
                srcb + (size_t)s_step[r] * (H_ * K_) + s_woff[r]);             \
            *reinterpret_cast<float4*>(dst + s_soff[r]) = val;                 \
        }                                                                      \
    }

    STAGE(0, 0);
    __syncthreads();

    int my_oct = ko * 80;

    #pragma unroll 1
    for (int c = 0; c < NCH; c++) {
        int buf = c & 1;
        if (c + 1 < NCH) STAGE(c + 1, buf ^ 1);

        const char* sb = smem + buf * BUFB;

        #pragma unroll 1
        for (int g = 0; g < CHQ; g++) {
            // ---- dots vs OLD h: k streams (kept in regs for the update) ----
            float4 kreg[4][4];
            float kax[4], kay[4], qax[4], qay[4];
            #pragma unroll
            for (int i = 0; i < 4; i++) { kax[i]=0.f; kay[i]=0.f; qax[i]=0.f; qay[i]=0.f; }

            #pragma unroll
            for (int i = 0; i < 4; i++) {
                const char* pi = sb + (4*g + i) * STEPB + my_oct;
                #pragma unroll
                for (int j = 0; j < 4; j++)
                    kreg[i][j] = *reinterpret_cast<const float4*>(pi + j*16);
            }
            #pragma unroll
            for (int i = 0; i < 4; i++) {
                #pragma unroll
                for (int j = 0; j < 4; j++) {
                    float4 kv = kreg[i][j];
                    kax[i] = fmaf(h[4*j+0].x, kv.x, kax[i]); kay[i] = fmaf(h[4*j+0].y, kv.x, kay[i]);
                    kax[i] = fmaf(h[4*j+1].x, kv.y, kax[i]); kay[i] = fmaf(h[4*j+1].y, kv.y, kay[i]);
                    kax[i] = fmaf(h[4*j+2].x, kv.z, kax[i]); kay[i] = fmaf(h[4*j+2].y, kv.z, kay[i]);
                    kax[i] = fmaf(h[4*j+3].x, kv.w, kax[i]); kay[i] = fmaf(h[4*j+3].y, kv.w, kay[i]);
                }
            }
            // ---- q streams: transient, accumulate and discard ----
            #pragma unroll
            for (int i = 0; i < 4; i++) {
                const char* pi = sb + (4*g + i) * STEPB + ROWB + my_oct;
                #pragma unroll
                for (int j = 0; j < 4; j++) {
                    float4 qv = *reinterpret_cast<const float4*>(pi + j*16);
                    qax[i] = fmaf(h[4*j+0].x, qv.x, qax[i]); qay[i] = fmaf(h[4*j+0].y, qv.x, qay[i]);
                    qax[i] = fmaf(h[4*j+1].x, qv.y, qax[i]); qay[i] = fmaf(h[4*j+1].y, qv.y, qay[i]);
                    qax[i] = fmaf(h[4*j+2].x, qv.z, qax[i]); qay[i] = fmaf(h[4*j+2].y, qv.z, qay[i]);
                    qax[i] = fmaf(h[4*j+3].x, qv.w, qax[i]); qay[i] = fmaf(h[4*j+3].y, qv.w, qay[i]);
                }
            }

            // ---- ONE batched reduce over the 8 K-octants ----
            #pragma unroll
            for (int m = 1; m <= 4; m <<= 1) {
                #pragma unroll
                for (int i = 0; i < 4; i++) {
                    kax[i] += __shfl_xor_sync(0xffffffffu, kax[i], m);
                    kay[i] += __shfl_xor_sync(0xffffffffu, kay[i], m);
                    qax[i] += __shfl_xor_sync(0xffffffffu, qax[i], m);
                    qay[i] += __shfl_xor_sync(0xffffffffu, qay[i], m);
                }
            }

            // ---- scalar cascade (cross terms precomputed) ----
            float4 dd0 = ddp[0], dd1 = ddp[1], dd2 = ddp[2], dd3 = ddp[3];
            float4 ge  = ggp[0], gB  = ggp[1];
            float2 v1 = vp[0], v2 = vp[VSTR], v3 = vp[2*VSTR], v4 = vp[3*VSTR];
            float K12=dd0.x, K13=dd0.y, K14=dd0.z, K23=dd0.w;
            float K24=dd1.x, K34=dd1.y, Q11=dd1.z, Q12=dd1.w;
            float Q13=dd2.x, Q14=dd2.y, Q22=dd2.z, Q23=dd2.w;
            float Q24=dd3.x, Q33=dd3.y, Q34=dd3.z, Q44=dd3.w;
            float e1=ge.x, e2=ge.y, e3=ge.z, e4=ge.w;
            float b1=gB.x, b2=gB.y, b3=gB.z, b4=gB.w;

            // col x
            float u1x = fmaf(-e1, kax[0], v1.x) * b1;
            float t2x = fmaf(u1x, K12, e1*kax[1]);
            float u2x = fmaf(-e2, t2x, v2.x) * b2;
            float t3x = fmaf(u2x, K23, e2*fmaf(u1x, K13, e1*kax[2]));
            float u3x = fmaf(-e3, t3x, v3.x) * b3;
            float t4x = fmaf(u3x, K34, e3*fmaf(u2x, K24, e2*fmaf(u1x, K14, e1*kax[3])));
            float u4x = fmaf(-e4, t4x, v4.x) * b4;
            // col y
            float u1y = fmaf(-e1, kay[0], v1.y) * b1;
            float t2y = fmaf(u1y, K12, e1*kay[1]);
            float u2y = fmaf(-e2, t2y, v2.y) * b2;
            float t3y = fmaf(u2y, K23, e2*fmaf(u1y, K13, e1*kay[2]));
            float u3y = fmaf(-e3, t3y, v3.y) * b3;
            float t4y = fmaf(u3y, K34, e3*fmaf(u2y, K24, e2*fmaf(u1y, K14, e1*kay[3])));
            float u4y = fmaf(-e4, t4y, v4.y) * b4;

            if (ko == 0) {
                float2 o1, o2, o3, o4;
                o1.x = fmaf(u1x, Q11, e1*qax[0]);
                o1.y = fmaf(u1y, Q11, e1*qay[0]);
                o2.x = fmaf(u2x, Q22, e2*fmaf(u1x, Q12, e1*qax[1]));
                o2.y = fmaf(u2y, Q22, e2*fmaf(u1y, Q12, e1*qay[1]));
                o3.x = fmaf(u3x, Q33, e3*fmaf(u2x, Q23, e2*fmaf(u1x, Q13, e1*qax[2])));
                o3.y = fmaf(u3y, Q33, e3*fmaf(u2y, Q23, e2*fmaf(u1y, Q13, e1*qay[2])));
                o4.x = fmaf(u4x, Q44, e4*fmaf(u3x, Q34, e3*fmaf(u2x, Q24, e2*fmaf(u1x, Q14, e1*qax[3]))));
                o4.y = fmaf(u4y, Q44, e4*fmaf(u3y, Q34, e3*fmaf(u2y, Q24, e2*fmaf(u1y, Q14, e1*qay[3]))));
                op[0]      = o1;
                op[VSTR]   = o2;
                op[2*VSTR] = o3;
                op[3*VSTR] = o4;
            }

            // ---- fused update: h = E*h + c1*k1 + c2*k2 + c3*k3 + c4*k4 ----
            float e43 = e4*e3, e432 = e43*e2, E = e432*e1;
            float c1x = e432*u1x, c2x = e43*u2x, c3x = e4*u3x, c4x = u4x;
            float c1y = e432*u1y, c2y = e43*u2y, c3y = e4*u3y, c4y = u4y;
            #pragma unroll
            for (int j = 0; j < 4; j++) {
                #pragma unroll
                for (int r = 0; r < 4; r++) {
                    float k1c = (r==0)?kreg[0][j].x:(r==1)?kreg[0][j].y:(r==2)?kreg[0][j].z:kreg[0][j].w;
                    float k2c = (r==0)?kreg[1][j].x:(r==1)?kreg[1][j].y:(r==2)?kreg[1][j].z:kreg[1][j].w;
                    float k3c = (r==0)?kreg[2][j].x:(r==1)?kreg[2][j].y:(r==2)?kreg[2][j].z:kreg[2][j].w;
                    float k4c = (r==0)?kreg[3][j].x:(r==1)?kreg[3][j].y:(r==2)?kreg[3][j].z:kreg[3][j].w;
                    float2 hr = h[4*j + r];
                    hr.x = fmaf(k4c, c4x, fmaf(k3c, c3x, fmaf(k2c, c2x, fmaf(k1c, c1x, E*hr.x))));
                    hr.y = fmaf(k4c, c4y, fmaf(k3c, c3y, fmaf(k2c, c2y, fmaf(k1c, c1y, E*hr.y))));
                    h[4*j + r] = hr;
                }
            }

            ddp += 4 * H_;
            ggp += 2 * HV_;
            vp  += 4 * VSTR;
            op  += 4 * VSTR;
        }

        __syncthreads();   // staging c+1 complete; compute c done before c+2 overwrites
    }
    #undef STAGE
}

// ---------------------------------------------------------------------------
// Inputs (metadata order): A_log, a, dt_bias, q, k, v, b,
//                          initial_state_source, initial_state_indices
// Output: float32 [B,T,HV,V]
// ---------------------------------------------------------------------------
extern "C" void kernel_launch(void* const* d_in, const int* in_sizes, int n_in,
                              void* d_out, int out_size) {
    const float* A_log = (const float*)d_in[0];
    const float* a     = (const float*)d_in[1];
    const float* dtb   = (const float*)d_in[2];
    const float* q     = (const float*)d_in[3];
    const float* k     = (const float*)d_in[4];
    const float* v     = (const float*)d_in[5];
    const float* bb    = (const float*)d_in[6];
    const float* h0    = (const float*)d_in[7];
    const int*   h0i   = (const int*)d_in[8];
    float* out = (float*)d_out;

    prep_qk<<<(B_ * T_ * H_) / 4, 128>>>(q, k);
    prep_dots4<<<(B_ * S4_ * H_) / 4, 128>>>();
    prep_gate8<<<((size_t)B_ * S4_ * HV_ + 255) / 256, 256>>>(A_log, a, dtb, bb);
    gdn_recurrent<<<B_ * HV_ * 2, 256>>>(v, h0, h0i, out);
}

// round 16
// speedup vs baseline: 1.1226x; 1.1226x over previous
#include <cuda_runtime.h>
#include <math.h>

#define B_  8
#define T_  4096
#define H_  4
#define HV_ 8
#define K_  128
#define V_  128
#define REP_ (HV_/H_)   // 2
#define S_  (T_/2)      // fused 2-step groups
#define CHS 16          // steps per smem chunk
#define CHG (CHS/2)     // groups per chunk = 8
#define NCH (T_/CHS)    // 256 chunks

// smem layout: stream row = 8 octants * 80B (16B pad) = 640B; step = 1280B.
#define ROWB  640
#define STEPB 1280
#define BUFB  (CHS*STEPB)   // 20480B per buffer, x2 double-buffered

// Scratch (static __device__ arrays: allocation-free per harness rules)
__device__ float  g_qn[(size_t)B_*T_*H_*K_];  // l2norm q * K^-0.5
__device__ float  g_kn[(size_t)B_*T_*H_*K_];  // l2norm k
__device__ float4 g_d  [(size_t)B_*S_*H_];    // {k1.q1, k1.k2, k1.q2, k2.q2}
__device__ float4 g_gb4[(size_t)B_*S_*HV_];   // {eg1, beta1, eg2, beta2}

// ---- f32x2 packed helpers (pairs are row-native here: few packs needed) ----
typedef unsigned long long u64t;
__device__ __forceinline__ u64t pkdup(float v) {
    u64t r; asm("mov.b64 %0,{%1,%1};" : "=l"(r) : "f"(v)); return r;
}
__device__ __forceinline__ u64t pk2(float lo, float hi) {
    u64t r; asm("mov.b64 %0,{%1,%2};" : "=l"(r) : "f"(lo), "f"(hi)); return r;
}
__device__ __forceinline__ float up2sum(u64t p) {
    float lo, hi; asm("mov.b64 {%0,%1},%2;" : "=f"(lo), "=f"(hi) : "l"(p));
    return lo + hi;
}
__device__ __forceinline__ u64t fma2(u64t a, u64t b, u64t c) {
    u64t d; asm("fma.rn.f32x2 %0,%1,%2,%3;" : "=l"(d) : "l"(a), "l"(b), "l"(c)); return d;
}
__device__ __forceinline__ u64t mul2(u64t a, u64t b) {
    u64t d; asm("mul.rn.f32x2 %0,%1,%2;" : "=l"(d) : "l"(a), "l"(b)); return d;
}

// ---------------------------------------------------------------------------
// Prepass 1: per (b,t,h) row — l2norm q and k over K=128, fold scale into q.
// ---------------------------------------------------------------------------
__global__ void __launch_bounds__(128) prep_qk(const float* __restrict__ q,
                                               const float* __restrict__ k) {
    int warp = threadIdx.x >> 5;
    int lane = threadIdx.x & 31;
    size_t row = (size_t)blockIdx.x * 4 + warp;
    const float4* q4 = reinterpret_cast<const float4*>(q + row * K_);
    const float4* k4 = reinterpret_cast<const float4*>(k + row * K_);
    float4 qa = q4[lane];
    float4 ka = k4[lane];
    float sq = qa.x*qa.x + qa.y*qa.y + qa.z*qa.z + qa.w*qa.w;
    float sk = ka.x*ka.x + ka.y*ka.y + ka.z*ka.z + ka.w*ka.w;
    #pragma unroll
    for (int o = 16; o > 0; o >>= 1) {
        sq += __shfl_xor_sync(0xffffffffu, sq, o);
        sk += __shfl_xor_sync(0xffffffffu, sk, o);
    }
    const float scale = 0.088388347648318440550f;   // 128^-0.5
    float iq = rsqrtf(sq + 1e-6f) * scale;
    float ik = rsqrtf(sk + 1e-6f);
    reinterpret_cast<float4*>(g_qn + row * K_)[lane] =
        make_float4(qa.x*iq, qa.y*iq, qa.z*iq, qa.w*iq);
    reinterpret_cast<float4*>(g_kn + row * K_)[lane] =
        make_float4(ka.x*ik, ka.y*ik, ka.z*ik, ka.w*ik);
}

// ---------------------------------------------------------------------------
// Prepass 1b: per group (b,s,h) — cross dots {k1.q1, k1.k2, k1.q2, k2.q2}.
// ---------------------------------------------------------------------------
__global__ void __launch_bounds__(128) prep_dots() {
    int warp = threadIdx.x >> 5;
    int lane = threadIdx.x & 31;
    size_t gid = (size_t)blockIdx.x * 4 + warp;      // (b*S + s)*H + hh
    size_t hh   = gid % H_;
    size_t row1 = (gid / H_) * 2 * H_ + hh;          // (b*T + 2s)*H + hh
    float4 k1 = reinterpret_cast<const float4*>(g_kn + row1 * K_)[lane];
    float4 q1 = reinterpret_cast<const float4*>(g_qn + row1 * K_)[lane];
    float4 k2 = reinterpret_cast<const float4*>(g_kn + (row1 + H_) * K_)[lane];
    float4 q2 = reinterpret_cast<const float4*>(g_qn + (row1 + H_) * K_)[lane];
    float d0 = k1.x*q1.x + k1.y*q1.y + k1.z*q1.z + k1.w*q1.w;
    float d1 = k1.x*k2.x + k1.y*k2.y + k1.z*k2.z + k1.w*k2.w;
    float d2 = k1.x*q2.x + k1.y*q2.y + k1.z*q2.z + k1.w*q2.w;
    float d3 = k2.x*q2.x + k2.y*q2.y + k2.z*q2.z + k2.w*q2.w;
    #pragma unroll
    for (int o = 16; o > 0; o >>= 1) {
        d0 += __shfl_xor_sync(0xffffffffu, d0, o);
        d1 += __shfl_xor_sync(0xffffffffu, d1, o);
        d2 += __shfl_xor_sync(0xffffffffu, d2, o);
        d3 += __shfl_xor_sync(0xffffffffu, d3, o);
    }
    if (lane == 0) g_d[gid] = make_float4(d0, d1, d2, d3);
}

// ---------------------------------------------------------------------------
// Prepass 2: per group (b,s,hv) — gates for both steps packed as one float4.
// ---------------------------------------------------------------------------
__global__ void __launch_bounds__(256) prep_gate4(const float* __restrict__ A_log,
                                                  const float* __restrict__ a,
                                                  const float* __restrict__ dt_bias,
                                                  const float* __restrict__ b) {
    size_t i = (size_t)blockIdx.x * blockDim.x + threadIdx.x;   // (b*S+s)*HV+hv
    if (i >= (size_t)B_*S_*HV_) return;
    int    hv = (int)(i % HV_);
    size_t bs = i / HV_;
    float  Ae = expf(A_log[hv]);
    float4 r;
    #pragma unroll
    for (int u = 0; u < 2; u++) {
        size_t idx = (2*bs + u) * HV_ + hv;
        float x  = a[idx] + dt_bias[hv];
        float sp = (x <= 20.0f) ? log1pf(expf(x)) : x;   // softplus
        float eg = expf(-Ae * sp);
        float bt = 1.0f / (1.0f + expf(-b[idx]));
        if (u == 0) { r.x = eg; r.y = bt; } else { r.z = eg; r.w = bt; }
    }
    g_gb4[i] = r;
}

// ---------------------------------------------------------------------------
// Main persistent recurrence: R11 structure (2-step fused, smem-staged,
// 256 thr, ko=tid&7, vg=tid>>3) with the inner math in packed f32x2,
// paired along the K-ROW axis so stream pairs come free from smem
// (ulonglong2 view) and state pairs are native (h2[col][rowpair]).
// FMA-pipe inst/thread/group: 244 -> 132.
// ---------------------------------------------------------------------------
__global__ void __launch_bounds__(256, 1) gdn_recurrent(
    const float* __restrict__ vin,
    const float* __restrict__ h0src,
    const int*   __restrict__ h0idx,
    float* __restrict__ out)
{
    __shared__ __align__(16) char smem[2 * BUFB];   // 40 KB

    int blk   = blockIdx.x;
    int vhalf = blk & 1;
    int hv    = (blk >> 1) & (HV_ - 1);
    int b     = blk >> 4;
    int tid   = threadIdx.x;
    int ko    = tid & 7;          // K-octant: rows [ko*16, ko*16+16)
    int vg    = tid >> 3;         // 0..31 -> V columns vg*2, vg*2+1
    int v0    = vhalf * 64 + vg * 2;
    int hh    = hv / REP_;

    // State: h2[c*8+rp] packs rows (ko*16+2rp, ko*16+2rp+1) of column v0+c.
    u64t h2[16];
    int idx = h0idx[b];
    if (idx >= 0) {
        const float* src = h0src + (((size_t)idx * HV_ + hv) * K_ + (size_t)ko * 16) * V_ + v0;
        #pragma unroll
        for (int rp = 0; rp < 8; rp++) {
            float2 r0 = *reinterpret_cast<const float2*>(src + (size_t)(2*rp  ) * V_);
            float2 r1 = *reinterpret_cast<const float2*>(src + (size_t)(2*rp+1) * V_);
            h2[rp]     = pk2(r0.x, r1.x);
            h2[8 + rp] = pk2(r0.y, r1.y);
        }
    } else {
        #pragma unroll
        for (int i = 0; i < 16; i++) h2[i] = 0ull;
    }

    const int VSTR = HV_ * V_ / 2;      // float2 stride per t-step

    const float*  kgm = g_kn + ((size_t)b*T_*H_ + hh)*K_;   // chunk staging bases
    const float*  qgm = g_qn + ((size_t)b*T_*H_ + hh)*K_;
    const float4* ddp = g_d   + (size_t)b*S_*H_  + hh;
    const float4* gbp = g_gb4 + (size_t)b*S_*HV_ + hv;
    const float2* vp  = reinterpret_cast<const float2*>(vin + ((size_t)b*T_*HV_ + hv)*V_ + v0);
    float2*       op  = reinterpret_cast<float2*>(out + ((size_t)b*T_*HV_ + hv)*V_ + v0);

    // Staging decode (identical to R11): 256 threads, 4 float4/thread/chunk.
    int s_step[4], s_soff[4], s_woff[4];
    #pragma unroll
    for (int r = 0; r < 4; r++) {
        int fidx = tid + 256 * r;
        int step = fidx >> 6;
        int w16  = fidx & 31;
        s_step[r] = step;
        s_woff[r] = w16 * 4;
        s_soff[r] = step * STEPB + ((fidx >> 5) & 1) * ROWB
                  + (w16 >> 2) * 80 + (w16 & 3) * 16;
    }

    #define STAGE(CH, BUF)                                                     \
    {                                                                          \
        const float* kb = kgm + (size_t)(CH) * CHS * (H_ * K_);                \
        const float* qb = qgm + (size_t)(CH) * CHS * (H_ * K_);                \
        char* dst = smem + (BUF) * BUFB;                                       \
        _Pragma("unroll")                                                      \
        for (int r = 0; r < 4; r++) {                                          \
            const float* srcb = ((tid + 256*r) & 32) ? qb : kb;                \
            float4 val = *reinterpret_cast<const float4*>(                     \
                srcb + (size_t)s_step[r] * (H_ * K_) + s_woff[r]);             \
            *reinterpret_cast<float4*>(dst + s_soff[r]) = val;                 \
        }                                                                      \
    }

    STAGE(0, 0);
    __syncthreads();

    int my_oct = ko * 80;

    #pragma unroll 1
    for (int c = 0; c < NCH; c++) {
        int buf = c & 1;
        if (c + 1 < NCH) STAGE(c + 1, buf ^ 1);

        const char* sb = smem + buf * BUFB;

        #pragma unroll 1
        for (int g = 0; g < CHG; g++) {
            const char* p1 = sb + (2*g    ) * STEPB + my_oct;
            const char* p2 = sb + (2*g + 1) * STEPB + my_oct;

            // k streams kept for the update; each 16B = 2 row-pairs.
            ulonglong2 k1u[4], k2u[4];
            #pragma unroll
            for (int j = 0; j < 4; j++) {
                k1u[j] = *reinterpret_cast<const ulonglong2*>(p1 + j*16);
                k2u[j] = *reinterpret_cast<const ulonglong2*>(p2 + j*16);
            }

            // 4 dots vs OLD h, both columns: 8 paired accumulators.
            u64t ak1x=0ull, ak1y=0ull, ak2x=0ull, ak2y=0ull;
            u64t aq1x=0ull, aq1y=0ull, aq2x=0ull, aq2y=0ull;
            #pragma unroll
            for (int j = 0; j < 4; j++) {
                ulonglong2 q1u = *reinterpret_cast<const ulonglong2*>(p1 + ROWB + j*16);
                ulonglong2 q2u = *reinterpret_cast<const ulonglong2*>(p2 + ROWB + j*16);
                u64t hx0 = h2[2*j], hx1 = h2[2*j+1];
                u64t hy0 = h2[8+2*j], hy1 = h2[8+2*j+1];
                ak1x = fma2(hx0, k1u[j].x, ak1x); ak1x = fma2(hx1, k1u[j].y, ak1x);
                ak1y = fma2(hy0, k1u[j].x, ak1y); ak1y = fma2(hy1, k1u[j].y, ak1y);
                ak2x = fma2(hx0, k2u[j].x, ak2x); ak2x = fma2(hx1, k2u[j].y, ak2x);
                ak2y = fma2(hy0, k2u[j].x, ak2y); ak2y = fma2(hy1, k2u[j].y, ak2y);
                aq1x = fma2(hx0, q1u.x, aq1x);    aq1x = fma2(hx1, q1u.y, aq1x);
                aq1y = fma2(hy0, q1u.x, aq1y);    aq1y = fma2(hy1, q1u.y, aq1y);
                aq2x = fma2(hx0, q2u.x, aq2x);    aq2x = fma2(hx1, q2u.y, aq2x);
                aq2y = fma2(hy0, q2u.x, aq2y);    aq2y = fma2(hy1, q2u.y, aq2y);
            }
            float k1x = up2sum(ak1x), k1y = up2sum(ak1y);
            float k2x = up2sum(ak2x), k2y = up2sum(ak2y);
            float q1x = up2sum(aq1x), q1y = up2sum(aq1y);
            float q2x = up2sum(aq2x), q2y = up2sum(aq2y);

            // Batched reduce over the 8 K-octants (lane bits 0..2)
            #pragma unroll
            for (int m = 1; m <= 4; m <<= 1) {
                k1x += __shfl_xor_sync(0xffffffffu, k1x, m);
                k1y += __shfl_xor_sync(0xffffffffu, k1y, m);
                k2x += __shfl_xor_sync(0xffffffffu, k2x, m);
                k2y += __shfl_xor_sync(0xffffffffu, k2y, m);
                q1x += __shfl_xor_sync(0xffffffffu, q1x, m);
                q1y += __shfl_xor_sync(0xffffffffu, q1y, m);
                q2x += __shfl_xor_sync(0xffffffffu, q2x, m);
                q2y += __shfl_xor_sync(0xffffffffu, q2y, m);
            }

            float4 dd = ddp[0];       // {k1.q1, k1.k2, k1.q2, k2.q2}
            float4 gg = gbp[0];       // {eg1, beta1, eg2, beta2}
            float2 v1 = vp[0];
            float2 v2 = vp[VSTR];
            float eg1 = gg.x, b1 = gg.y, eg2 = gg.z, b2 = gg.w;

            float u1x = fmaf(-eg1, k1x, v1.x) * b1;
            float u1y = fmaf(-eg1, k1y, v1.y) * b1;
            float hk2x = fmaf(u1x, dd.y, eg1 * k2x);
            float hk2y = fmaf(u1y, dd.y, eg1 * k2y);
            float u2x = fmaf(-eg2, hk2x, v2.x) * b2;
            float u2y = fmaf(-eg2, hk2y, v2.y) * b2;

            if (ko == 0) {
                float2 o1, o2;
                o1.x = fmaf(eg1, q1x, u1x * dd.x);
                o1.y = fmaf(eg1, q1y, u1y * dd.x);
                float hq2x = fmaf(u1x, dd.z, eg1 * q2x);
                float hq2y = fmaf(u1y, dd.z, eg1 * q2y);
                o2.x = fmaf(eg2, hq2x, u2x * dd.w);
                o2.y = fmaf(eg2, hq2y, u2y * dd.w);
                op[0]    = o1;
                op[VSTR] = o2;
            }

            // Fused update: h = (eg1*eg2)h + (eg2*u1)k1 + u2*k2, paired rows.
            float e12 = eg1 * eg2;
            u64t E2  = pkdup(e12);
            u64t c1x2 = pkdup(eg2 * u1x), c1y2 = pkdup(eg2 * u1y);
            u64t u2x2 = pkdup(u2x),       u2y2 = pkdup(u2y);
            #pragma unroll
            for (int j = 0; j < 4; j++) {
                h2[2*j]     = fma2(k2u[j].x, u2x2, fma2(k1u[j].x, c1x2, mul2(h2[2*j],     E2)));
                h2[2*j+1]   = fma2(k2u[j].y, u2x2, fma2(k1u[j].y, c1x2, mul2(h2[2*j+1],   E2)));
                h2[8+2*j]   = fma2(k2u[j].x, u2y2, fma2(k1u[j].x, c1y2, mul2(h2[8+2*j],   E2)));
                h2[8+2*j+1] = fma2(k2u[j].y, u2y2, fma2(k1u[j].y, c1y2, mul2(h2[8+2*j+1], E2)));
            }

            ddp += H_;
            gbp += HV_;
            vp  += 2 * VSTR;
            op  += 2 * VSTR;
        }

        __syncthreads();   // staging c+1 complete; compute c done before c+2 overwrites
    }
    #undef STAGE
}

// ---------------------------------------------------------------------------
// Inputs (metadata order): A_log, a, dt_bias, q, k, v, b,
//                          initial_state_source, initial_state_indices
// Output: float32 [B,T,HV,V]
// ---------------------------------------------------------------------------
extern "C" void kernel_launch(void* const* d_in, const int* in_sizes, int n_in,
                              void* d_out, int out_size) {
    const float* A_log = (const float*)d_in[0];
    const float* a     = (const float*)d_in[1];
    const float* dtb   = (const float*)d_in[2];
    const float* q     = (const float*)d_in[3];
    const float* k     = (const float*)d_in[4];
    const float* v     = (const float*)d_in[5];
    const float* bb    = (const float*)d_in[6];
    const float* h0    = (const float*)d_in[7];
    const int*   h0i   = (const int*)d_in[8];
    float* out = (float*)d_out;

    prep_qk<<<(B_ * T_ * H_) / 4, 128>>>(q, k);
    prep_dots<<<(B_ * S_ * H_) / 4, 128>>>();
    prep_gate4<<<((size_t)B_ * S_ * HV_ + 255) / 256, 256>>>(A_log, a, dtb, bb);
    gdn_recurrent<<<B_ * HV_ * 2, 256>>>(v, h0, h0i, out);
}

// round 17
// speedup vs baseline: 1.1230x; 1.0004x over previous
#include <cuda_runtime.h>
#include <math.h>

#define B_  8
#define T_  4096
#define H_  4
#define HV_ 8
#define K_  128
#define V_  128
#define REP_ (HV_/H_)   // 2
#define S_  (T_/2)      // fused 2-step groups
#define CHS 16          // steps per smem chunk
#define CHG (CHS/2)     // groups per chunk = 8
#define NCH (T_/CHS)    // 256 chunks

// smem: per step, k row (512B) + q row (512B); 32 16B-slots per row, swizzled.
#define STEPB 1024
#define BUFB  (CHS*STEPB)   // 16KB per buffer, x2 double-buffered

// Scratch (static __device__ arrays: allocation-free per harness rules)
__device__ float  g_qn[(size_t)B_*T_*H_*K_];  // l2norm q * K^-0.5
__device__ float  g_kn[(size_t)B_*T_*H_*K_];  // l2norm k
__device__ float4 g_d  [(size_t)B_*S_*H_];    // {k1.q1, k1.k2, k1.q2, k2.q2}
__device__ float4 g_gb4[(size_t)B_*S_*HV_];   // {eg1, beta1, eg2, beta2}

// slot swizzle (involution, injective): even/odd slot sets each hit every
// bank-quad exactly twice -> 2-phase LDS.128, 4-phase staging STS.
__device__ __forceinline__ int SWZ(int s) { return s ^ ((s >> 3) & 1); }

// ---- f32x2 packed helpers ----
typedef unsigned long long u64t;
__device__ __forceinline__ u64t pkdup(float v) {
    u64t r; asm("mov.b64 %0,{%1,%1};" : "=l"(r) : "f"(v)); return r;
}
__device__ __forceinline__ u64t pk2(float lo, float hi) {
    u64t r; asm("mov.b64 %0,{%1,%2};" : "=l"(r) : "f"(lo), "f"(hi)); return r;
}
__device__ __forceinline__ float up2sum(u64t p) {
    float lo, hi; asm("mov.b64 {%0,%1},%2;" : "=f"(lo), "=f"(hi) : "l"(p));
    return lo + hi;
}
__device__ __forceinline__ u64t fma2(u64t a, u64t b, u64t c) {
    u64t d; asm("fma.rn.f32x2 %0,%1,%2,%3;" : "=l"(d) : "l"(a), "l"(b), "l"(c)); return d;
}
__device__ __forceinline__ u64t mul2(u64t a, u64t b) {
    u64t d; asm("mul.rn.f32x2 %0,%1,%2;" : "=l"(d) : "l"(a), "l"(b)); return d;
}

// ---------------------------------------------------------------------------
// Prepass 1: per (b,t,h) row — l2norm q and k over K=128, fold scale into q.
// ---------------------------------------------------------------------------
__global__ void __launch_bounds__(128) prep_qk(const float* __restrict__ q,
                                               const float* __restrict__ k) {
    int warp = threadIdx.x >> 5;
    int lane = threadIdx.x & 31;
    size_t row = (size_t)blockIdx.x * 4 + warp;
    float4 qa = reinterpret_cast<const float4*>(q + row * K_)[lane];
    float4 ka = reinterpret_cast<const float4*>(k + row * K_)[lane];
    float sq = qa.x*qa.x + qa.y*qa.y + qa.z*qa.z + qa.w*qa.w;
    float sk = ka.x*ka.x + ka.y*ka.y + ka.z*ka.z + ka.w*ka.w;
    #pragma unroll
    for (int o = 16; o > 0; o >>= 1) {
        sq += __shfl_xor_sync(0xffffffffu, sq, o);
        sk += __shfl_xor_sync(0xffffffffu, sk, o);
    }
    const float scale = 0.088388347648318440550f;   // 128^-0.5
    float iq = rsqrtf(sq + 1e-6f) * scale;
    float ik = rsqrtf(sk + 1e-6f);
    reinterpret_cast<float4*>(g_qn + row * K_)[lane] =
        make_float4(qa.x*iq, qa.y*iq, qa.z*iq, qa.w*iq);
    reinterpret_cast<float4*>(g_kn + row * K_)[lane] =
        make_float4(ka.x*ik, ka.y*ik, ka.z*ik, ka.w*ik);
}

// ---------------------------------------------------------------------------
// Prepass 1b: per group (b,s,h) — cross dots {k1.q1, k1.k2, k1.q2, k2.q2}.
// ---------------------------------------------------------------------------
__global__ void __launch_bounds__(128) prep_dots() {
    int warp = threadIdx.x >> 5;
    int lane = threadIdx.x & 31;
    size_t gid = (size_t)blockIdx.x * 4 + warp;      // (b*S + s)*H + hh
    size_t hh   = gid % H_;
    size_t row1 = (gid / H_) * 2 * H_ + hh;          // (b*T + 2s)*H + hh
    float4 k1 = reinterpret_cast<const float4*>(g_kn + row1 * K_)[lane];
    float4 q1 = reinterpret_cast<const float4*>(g_qn + row1 * K_)[lane];
    float4 k2 = reinterpret_cast<const float4*>(g_kn + (row1 + H_) * K_)[lane];
    float4 q2 = reinterpret_cast<const float4*>(g_qn + (row1 + H_) * K_)[lane];
    float d0 = k1.x*q1.x + k1.y*q1.y + k1.z*q1.z + k1.w*q1.w;
    float d1 = k1.x*k2.x + k1.y*k2.y + k1.z*k2.z + k1.w*k2.w;
    float d2 = k1.x*q2.x + k1.y*q2.y + k1.z*q2.z + k1.w*q2.w;
    float d3 = k2.x*q2.x + k2.y*q2.y + k2.z*q2.z + k2.w*q2.w;
    #pragma unroll
    for (int o = 16; o > 0; o >>= 1) {
        d0 += __shfl_xor_sync(0xffffffffu, d0, o);
        d1 += __shfl_xor_sync(0xffffffffu, d1, o);
        d2 += __shfl_xor_sync(0xffffffffu, d2, o);
        d3 += __shfl_xor_sync(0xffffffffu, d3, o);
    }
    if (lane == 0) g_d[gid] = make_float4(d0, d1, d2, d3);
}

// ---------------------------------------------------------------------------
// Prepass 2: per group (b,s,hv) — gates for both steps packed as one float4.
// ---------------------------------------------------------------------------
__global__ void __launch_bounds__(256) prep_gate4(const float* __restrict__ A_log,
                                                  const float* __restrict__ a,
                                                  const float* __restrict__ dt_bias,
                                                  const float* __restrict__ b) {
    size_t i = (size_t)blockIdx.x * blockDim.x + threadIdx.x;   // (b*S+s)*HV+hv
    if (i >= (size_t)B_*S_*HV_) return;
    int    hv = (int)(i % HV_);
    size_t bs = i / HV_;
    float  Ae = expf(A_log[hv]);
    float4 r;
    #pragma unroll
    for (int u = 0; u < 2; u++) {
        size_t idx = (2*bs + u) * HV_ + hv;
        float x  = a[idx] + dt_bias[hv];
        float sp = (x <= 20.0f) ? log1pf(expf(x)) : x;   // softplus
        float eg = expf(-Ae * sp);
        float bt = 1.0f / (1.0f + expf(-b[idx]));
        if (u == 0) { r.x = eg; r.y = bt; } else { r.z = eg; r.w = bt; }
    }
    g_gb4[i] = r;
}

// ---------------------------------------------------------------------------
// Main persistent recurrence: 2-step fused, smem-staged, f32x2, 512 threads
// (16 warps/CTA -> 4 warps/SMSP for latency hiding).
//   lane16 = tid&15: K-sixteenth (8 rows = 4 row-pairs/col)
//   vg     = tid>>4: 2 adjacent V columns (v0 = vhalf*64 + vg*2)
// Per group: 8 f32x2 dot accumulators (k1,k2,q1,q2 x 2 cols) -> 16-lane
// reduce-scatter (8 shfl) -> 3-shfl gather + SEL demux -> per-lane cascade
// (col = lane16&1, redundant x8) -> 4-shfl u-broadcast -> paired update.
// ---------------------------------------------------------------------------
__global__ void __launch_bounds__(512, 1) gdn_recurrent(
    const float* __restrict__ vin,
    const float* __restrict__ h0src,
    const int*   __restrict__ h0idx,
    float* __restrict__ out)
{
    __shared__ __align__(16) char smem[2 * BUFB];   // 32 KB

    int blk   = blockIdx.x;
    int vhalf = blk & 1;
    int hv    = (blk >> 1) & (HV_ - 1);
    int b     = blk >> 4;
    int tid   = threadIdx.x;
    int l16   = tid & 15;         // K-sixteenth: rows [l16*8, l16*8+8)
    int vg    = tid >> 4;         // 0..31 -> V columns vg*2, vg*2+1
    int c0    = l16 & 1;          // cascade column owned by this lane
    int s0    = (l16 >> 1) & 3;   // stream id this lane ends holding
    int v0    = vhalf * 64 + vg * 2;
    int hh    = hv / REP_;

    // State: h2[c*4+rp] packs rows (l16*8+2rp, l16*8+2rp+1) of column v0+c.
    u64t h2[8];
    int idx = h0idx[b];
    if (idx >= 0) {
        const float* src = h0src + (((size_t)idx * HV_ + hv) * K_ + (size_t)l16 * 8) * V_ + v0;
        #pragma unroll
        for (int rp = 0; rp < 4; rp++) {
            float2 r0 = *reinterpret_cast<const float2*>(src + (size_t)(2*rp  ) * V_);
            float2 r1 = *reinterpret_cast<const float2*>(src + (size_t)(2*rp+1) * V_);
            h2[rp]     = pk2(r0.x, r1.x);
            h2[4 + rp] = pk2(r0.y, r1.y);
        }
    } else {
        #pragma unroll
        for (int i = 0; i < 8; i++) h2[i] = 0ull;
    }

    const int VSTR = HV_ * V_;          // float stride per t-step

    const float*  kgm = g_kn + ((size_t)b*T_*H_ + hh)*K_;
    const float*  qgm = g_qn + ((size_t)b*T_*H_ + hh)*K_;
    const float4* ddp = g_d   + (size_t)b*S_*H_  + hh;
    const float4* gbp = g_gb4 + (size_t)b*S_*HV_ + hv;
    const float*  vcp = vin + ((size_t)b*T_*HV_ + hv)*V_ + v0 + c0;   // per-lane col
    float*        ocp = out + ((size_t)b*T_*HV_ + hv)*V_ + v0 + c0;

    // Staging decode: chunk = 16 steps x 2 streams x 32 slots = 1024 float4;
    // 512 threads -> 2 per thread. fidx = tid + 512r.
    int s_gmo[2], s_smo[2];
    #pragma unroll
    for (int r = 0; r < 2; r++) {
        int fidx = tid + 512 * r;
        int step = fidx >> 6;
        int strm = (fidx >> 5) & 1;
        int s    = fidx & 31;
        s_gmo[r] = step * (H_ * K_) + s * 4;
        s_smo[r] = step * STEPB + strm * 512 + SWZ(s) * 16;
    }

    #define STAGE(CH, BUF)                                                     \
    {                                                                          \
        const float* kb = kgm + (size_t)(CH) * CHS * (H_ * K_);                \
        const float* qb = qgm + (size_t)(CH) * CHS * (H_ * K_);                \
        char* dst = smem + (BUF) * BUFB;                                       \
        _Pragma("unroll")                                                      \
        for (int r = 0; r < 2; r++) {                                          \
            const float* srcb = ((tid + 512*r) & 32) ? qb : kb;                \
            float4 val = *reinterpret_cast<const float4*>(srcb + s_gmo[r]);    \
            *reinterpret_cast<float4*>(dst + s_smo[r]) = val;                  \
        }                                                                      \
    }

    STAGE(0, 0);
    __syncthreads();

    int my1 = SWZ(2*l16)     * 16;   // first 16B of this lane's 32B slice
    int my2 = SWZ(2*l16 + 1) * 16;   // second 16B

    #pragma unroll 1
    for (int c = 0; c < NCH; c++) {
        int buf = c & 1;
        if (c + 1 < NCH) STAGE(c + 1, buf ^ 1);

        const char* sb = smem + buf * BUFB;

        #pragma unroll 1
        for (int g = 0; g < CHG; g++) {
            const char* base1 = sb + (2*g    ) * STEPB;
            const char* base2 = sb + (2*g + 1) * STEPB;

            // k slices kept for the update (row-pairs come free as u64)
            ulonglong2 k1a = *reinterpret_cast<const ulonglong2*>(base1 + my1);
            ulonglong2 k1b = *reinterpret_cast<const ulonglong2*>(base1 + my2);
            ulonglong2 k2a = *reinterpret_cast<const ulonglong2*>(base2 + my1);
            ulonglong2 k2b = *reinterpret_cast<const ulonglong2*>(base2 + my2);
            ulonglong2 q1a = *reinterpret_cast<const ulonglong2*>(base1 + 512 + my1);
            ulonglong2 q1b = *reinterpret_cast<const ulonglong2*>(base1 + 512 + my2);
            ulonglong2 q2a = *reinterpret_cast<const ulonglong2*>(base2 + 512 + my1);
            ulonglong2 q2b = *reinterpret_cast<const ulonglong2*>(base2 + 512 + my2);

            // Dots vs OLD h: A[vi], vi = stream*2 + col. 32 fma2, 8 chains.
            u64t A0=0ull,A1=0ull,A2=0ull,A3=0ull,A4=0ull,A5=0ull,A6=0ull,A7=0ull;
            #pragma unroll
            for (int rp = 0; rp < 4; rp++) {
                u64t p1 = (rp==0)?k1a.x:(rp==1)?k1a.y:(rp==2)?k1b.x:k1b.y;
                u64t p2 = (rp==0)?k2a.x:(rp==1)?k2a.y:(rp==2)?k2b.x:k2b.y;
                u64t pq1= (rp==0)?q1a.x:(rp==1)?q1a.y:(rp==2)?q1b.x:q1b.y;
                u64t pq2= (rp==0)?q2a.x:(rp==1)?q2a.y:(rp==2)?q2b.x:q2b.y;
                u64t h0c = h2[rp], h1c = h2[4+rp];
                A0 = fma2(h0c, p1,  A0);  A1 = fma2(h1c, p1,  A1);
                A2 = fma2(h0c, p2,  A2);  A3 = fma2(h1c, p2,  A3);
                A4 = fma2(h0c, pq1, A4);  A5 = fma2(h1c, pq1, A5);
                A6 = fma2(h0c, pq2, A6);  A7 = fma2(h1c, pq2, A7);
            }
            float a0 = up2sum(A0), a1 = up2sum(A1), a2 = up2sum(A2), a3 = up2sum(A3);
            float a4 = up2sum(A4), a5 = up2sum(A5), a6 = up2sum(A6), a7 = up2sum(A7);

            // ---- reduce-scatter over 16 lanes (masks 1,2,4,8): 8 shfl ----
            // round m=1 (vi bit0 = col; keep matching c0)
            float kp0 = c0 ? a1 : a0, gv0 = c0 ? a0 : a1;
            float kp1 = c0 ? a3 : a2, gv1 = c0 ? a2 : a3;
            float kp2 = c0 ? a5 : a4, gv2 = c0 ? a4 : a5;
            float kp3 = c0 ? a7 : a6, gv3 = c0 ? a6 : a7;
            float b40 = kp0 + __shfl_xor_sync(0xffffffffu, gv0, 1);
            float b41 = kp1 + __shfl_xor_sync(0xffffffffu, gv1, 1);
            float b42 = kp2 + __shfl_xor_sync(0xffffffffu, gv2, 1);
            float b43 = kp3 + __shfl_xor_sync(0xffffffffu, gv3, 1);
            // round m=2 (vi bit1; keep matching l16 bit1)
            int t2 = l16 & 2;
            float kq0 = t2 ? b41 : b40, gw0 = t2 ? b40 : b41;
            float kq1 = t2 ? b43 : b42, gw1 = t2 ? b42 : b43;
            float b20 = kq0 + __shfl_xor_sync(0xffffffffu, gw0, 2);
            float b21 = kq1 + __shfl_xor_sync(0xffffffffu, gw1, 2);
            // round m=4 (vi bit2; keep matching l16 bit2)
            int t4 = l16 & 4;
            float kr = t4 ? b21 : b20, gx = t4 ? b20 : b21;
            float T = kr + __shfl_xor_sync(0xffffffffu, gx, 4);
            // combine the two 8-lane subgroups (lane l, l^8 hold same vi)
            T += __shfl_xor_sync(0xffffffffu, T, 8);
            // now T = total[vi = l16&7], vi = stream*2 + col

            // ---- gather all 4 stream totals for this lane's col (3 shfl) ----
            float r2 = __shfl_xor_sync(0xffffffffu, T, 2);    // stream s0^1
            float r4 = __shfl_xor_sync(0xffffffffu, T, 4);    // stream s0^2
            float r6 = __shfl_xor_sync(0xffffffffu, r2, 4);   // stream s0^3
            bool sb1 = (s0 & 1), sb2 = (s0 & 2);
            float t01  = sb1 ? r2 : T,  t23  = sb1 ? r6 : r4;
            float t01b = sb1 ? T  : r2, t23b = sb1 ? r4 : r6;
            float k1t = sb2 ? t23  : t01;    // stream 0 total
            float k2t = sb2 ? t23b : t01b;   // stream 1
            float q1t = sb2 ? t01  : t23;    // stream 2
            float q2t = sb2 ? t01b : t23b;   // stream 3

            // ---- per-lane cascade for col c0 (redundant x8) ----
            float4 dd = ddp[0];       // {k1.q1, k1.k2, k1.q2, k2.q2}
            float4 gg = gbp[0];       // {eg1, beta1, eg2, beta2}
            float v1 = vcp[0];
            float v2 = vcp[VSTR];
            float eg1 = gg.x, bt1 = gg.y, eg2 = gg.z, bt2 = gg.w;

            float u1  = fmaf(-eg1, k1t, v1) * bt1;
            float hk2 = fmaf(u1, dd.y, eg1 * k2t);
            float u2  = fmaf(-eg2, hk2, v2) * bt2;

            if (l16 < 2) {     // lane 0 -> col v0, lane 1 -> col v0+1
                float o1  = fmaf(eg1, q1t, u1 * dd.x);
                float hq2 = fmaf(u1, dd.z, eg1 * q2t);
                float o2  = fmaf(eg2, hq2, u2 * dd.w);
                ocp[0]    = o1;
                ocp[VSTR] = o2;
            }

            // ---- broadcast u1,u2 for both cols (4 shfl, width 16) ----
            float u1c0 = __shfl_sync(0xffffffffu, u1, 0, 16);
            float u1c1 = __shfl_sync(0xffffffffu, u1, 1, 16);
            float u2c0 = __shfl_sync(0xffffffffu, u2, 0, 16);
            float u2c1 = __shfl_sync(0xffffffffu, u2, 1, 16);

            // ---- paired update: h = (eg1*eg2)h + (eg2*u1)k1 + u2*k2 ----
            u64t E2   = pkdup(eg1 * eg2);
            u64t c1c0 = pkdup(eg2 * u1c0), c1c1 = pkdup(eg2 * u1c1);
            u64t u20  = pkdup(u2c0),       u21  = pkdup(u2c1);
            #pragma unroll
            for (int rp = 0; rp < 4; rp++) {
                u64t p1 = (rp==0)?k1a.x:(rp==1)?k1a.y:(rp==2)?k1b.x:k1b.y;
                u64t p2 = (rp==0)?k2a.x:(rp==1)?k2a.y:(rp==2)?k2b.x:k2b.y;
                h2[rp]   = fma2(p2, u20, fma2(p1, c1c0, mul2(h2[rp],   E2)));
                h2[4+rp] = fma2(p2, u21, fma2(p1, c1c1, mul2(h2[4+rp], E2)));
            }

            ddp += H_;
            gbp += HV_;
            vcp += 2 * VSTR;
            ocp += 2 * VSTR;
        }

        __syncthreads();   // staging c+1 complete; compute c done before c+2 overwrites
    }
    #undef STAGE
}

// ---------------------------------------------------------------------------
// Inputs (metadata order): A_log, a, dt_bias, q, k, v, b,
//                          initial_state_source, initial_state_indices
// Output: float32 [B,T,HV,V]
// ---------------------------------------------------------------------------
extern "C" void kernel_launch(void* const* d_in, const int* in_sizes, int n_in,
                              void* d_out, int out_size) {
    const float* A_log = (const float*)d_in[0];
    const float* a     = (const float*)d_in[1];
    const float* dtb   = (const float*)d_in[2];
    const float* q     = (const float*)d_in[3];
    const float* k     = (const float*)d_in[4];
    const float* v     = (const float*)d_in[5];
    const float* bb    = (const float*)d_in[6];
    const float* h0    = (const float*)d_in[7];
    const int*   h0i   = (const int*)d_in[8];
    float* out = (float*)d_out;

    prep_qk<<<(B_ * T_ * H_) / 4, 128>>>(q, k);
    prep_dots<<<(B_ * S_ * H_) / 4, 128>>>();
    prep_gate4<<<((size_t)B_ * S_ * HV_ + 255) / 256, 256>>>(A_log, a, dtb, bb);
    gdn_recurrent<<<B_ * HV_ * 2, 512>>>(v, h0, h0i, out);
}